// round 6
// baseline (speedup 1.0000x reference)
#include <cuda_runtime.h>
#include <cuda_bf16.h>
#include <math_constants.h>

// Problem dims (fixed by reference setup_inputs)
#define B      128
#define IN     784
#define H      400
#define OUT    10
#define NQ     100             // H/4 neuron quads
#define BG     64              // batches per block
#define ES     6               // event segments (8 chunks = 128 events each)
#define NW     25              // ceil(784/32) bit words per batch
#define NTHR   (ES * BG)       // 384 threads
#define NWARP  (NTHR / 32)     // 12 warps
#define GRID_N (NQ * (B / BG)) // 200 blocks

#define THRESH 0.5f
#define DECAY  0.2f

// Scratch (allocation-free rule: __device__ globals)
__device__ float    g_spk[B * H];     // h1 spikes as floats
__device__ float    g_pmax[NQ * B];   // per-(quad,batch) layer1 max partial
__device__ float    g_pmin[NQ * B];
__device__ unsigned g_bar;            // device-wide barrier (self-resetting)

// ---- packed f32x2 helpers (4 floats in 2x 64-bit regs) ----------------------
struct P4 { unsigned long long a, b; };

__device__ __forceinline__ P4 p4_zero() { P4 r; r.a = 0ull; r.b = 0ull; return r; }

__device__ __forceinline__ P4 p4_pack(float x, float y, float z, float w) {
    P4 r;
    asm("mov.b64 %0, {%2, %3};\n\tmov.b64 %1, {%4, %5};"
        : "=l"(r.a), "=l"(r.b) : "f"(x), "f"(y), "f"(z), "f"(w));
    return r;
}
__device__ __forceinline__ float4 p4_unpack(P4 p) {
    float4 v;
    asm("mov.b64 {%0, %1}, %4;\n\tmov.b64 {%2, %3}, %5;"
        : "=f"(v.x), "=f"(v.y), "=f"(v.z), "=f"(v.w) : "l"(p.a), "l"(p.b));
    return v;
}
__device__ __forceinline__ P4 p4_add(P4 u, P4 v) {
    P4 r;
    asm("add.rn.f32x2 %0, %2, %3;\n\tadd.rn.f32x2 %1, %4, %5;"
        : "=l"(r.a), "=l"(r.b) : "l"(u.a), "l"(v.a), "l"(u.b), "l"(v.b));
    return r;
}

// ---------------------------------------------------------------------------
// chunk16: 16 consecutive events, 4 neurons. Identical numerics to the
// R5-passing kernel: sign-mask gating, running packed prefix qp for per-leaf
// max/min snapshots, balanced-16 pairwise tree via leaf-level binary counter.
// ---------------------------------------------------------------------------
__device__ __forceinline__ P4 chunk16(
    unsigned half, const float4* __restrict__ sW, int ebase,
    P4& qp, float4& mx, float4& mn)
{
    P4 k1, k2, k4, k8, out;
#pragma unroll
    for (int j = 0; j < 16; ++j) {
        int msk = ((int)(half << (31 - j))) >> 31;   // all-ones if bit j set
        float4 w = sW[ebase + j];
        float tx = __int_as_float(msk & __float_as_int(w.x));
        float ty = __int_as_float(msk & __float_as_int(w.y));
        float tz = __int_as_float(msk & __float_as_int(w.z));
        float tw = __int_as_float(msk & __float_as_int(w.w));
        P4 tp = p4_pack(tx, ty, tz, tw);
        qp = p4_add(qp, tp);                         // exact when gated off
        float4 q = p4_unpack(qp);
        mx.x = fmaxf(mx.x, q.x); mx.y = fmaxf(mx.y, q.y);
        mx.z = fmaxf(mx.z, q.z); mx.w = fmaxf(mx.w, q.w);
        mn.x = fminf(mn.x, q.x); mn.y = fminf(mn.y, q.y);
        mn.z = fminf(mn.z, q.z); mn.w = fminf(mn.w, q.w);
        if ((j & 1) == 0) {
            k1 = tp;
        } else {
            P4 s = p4_add(k1, tp);
            if ((j & 2) == 0) k2 = s;
            else {
                s = p4_add(k2, s);
                if ((j & 4) == 0) k4 = s;
                else {
                    s = p4_add(k4, s);
                    if (j == 7) k8 = s;
                    else out = p4_add(k8, s);        // j == 15
                }
            }
        }
    }
    return out;
}

// ---------------------------------------------------------------------------
// chunk16 for layer 2 (1 neuron): gate = spike float (exactly 0.0/1.0).
// ---------------------------------------------------------------------------
__device__ __forceinline__ float chunk16_l2(
    const float* __restrict__ spk, const float* __restrict__ w2, int ebase,
    float& q, float& mx, float& mn)
{
    float s[16];
#pragma unroll
    for (int j = 0; j < 16; ++j) {
        float t = spk[ebase + j] * w2[ebase + j];   // exact: 0 or w
        q += t;
        mx = fmaxf(mx, q);
        mn = fminf(mn, q);
        s[j] = t;
    }
#pragma unroll
    for (int st = 1; st < 16; st <<= 1)
#pragma unroll
        for (int j = 0; j < 16; j += 2 * st) s[j] += s[j + st];
    return s[0];
}

// ---------------------------------------------------------------------------
// Single fused kernel: pack -> layer1 -> device barrier -> layer2.
// Grid (NQ, B/BG) = (100, 2), 384 threads.
//   Block (qi, bg): 4 neurons [4qi,4qi+4), 64 batches [64bg, 64bg+64).
//   After the barrier, blocks with linear id < 128 finalize batch = linear.
// ---------------------------------------------------------------------------
__global__ __launch_bounds__(NTHR, 2) void k_fused(
    const float* __restrict__ input_vec,
    const float* __restrict__ W1,
    const float* __restrict__ W2,
    const float* __restrict__ h1_mem0,
    const float* __restrict__ h2_mem0,
    float* __restrict__ out)
{
    __shared__ float4   sW[IN];              // sW[e] = (w_n0..w_n3)[e]
    __shared__ unsigned s_bits[NW][BG];      // [word][local batch]
    __shared__ float4   s_tree[ES][BG];
    __shared__ float4   s_px[ES][BG];
    __shared__ float4   s_pn[ES][BG];
    __shared__ float4   s_L[BG];
    // layer2 smem
    __shared__ float    l2_spk[H];
    __shared__ float    l2_t[4][OUT], l2_px[4][OUT], l2_pn[4][OUT];
    __shared__ float    l2_fmx[NWARP], l2_fmn[NWARP];
    __shared__ float    l2_nmx[OUT], l2_nmn[OUT];

    const int t    = threadIdx.x;
    const int warp = t >> 5;
    const int lane = t & 31;
    const int n0   = blockIdx.x * 4;
    const int bg   = blockIdx.y;

    float* out_h2s   = out;                            // B*OUT
    float* out_smax  = out + B * OUT;                  // B
    float* out_smin  = out + B * OUT + B;              // B
    float* out_h1mem = out + B * OUT + 2 * B;          // B*H
    float* out_h2mem = out + B * OUT + 2 * B + B * H;  // B*OUT

    // -- Phase 0a: pack input bits into smem (task = (local batch, word group of 5))
    for (int task = warp; task < BG * 5; task += NWARP) {
        int b_l = task / 5;
        int wg  = task % 5;
        const float* row = input_vec + (bg * BG + b_l) * IN;
        unsigned m[5];
#pragma unroll
        for (int k = 0; k < 5; ++k) {
            int e = (wg * 5 + k) * 32 + lane;
            float v = (e < IN) ? row[e] : 0.0f;
            m[k] = __ballot_sync(0xffffffffu, v != 0.0f);
        }
        if (lane == 0) {
#pragma unroll
            for (int k = 0; k < 5; ++k) s_bits[wg * 5 + k][b_l] = m[k];
        }
    }
    // -- Phase 0b: stage weights
    for (int i = t; i < 4 * IN; i += NTHR) {
        int c = i / IN;
        int e = i - c * IN;
        ((float*)sW)[e * 4 + c] = W1[(n0 + c) * IN + e];
    }
    __syncthreads();

    // -- Phase 1: layer 1 (segmented JAX-tree scan, identical to R5)
    {
        const int seg = t / BG;                 // 0..5
        const int bl  = t % BG;
        const int b   = bg * BG + bl;

        P4 qp = p4_zero();
        float4 mx = make_float4(-CUDART_INF_F, -CUDART_INF_F, -CUDART_INF_F, -CUDART_INF_F);
        float4 mn = make_float4( CUDART_INF_F,  CUDART_INF_F,  CUDART_INF_F,  CUDART_INF_F);
        P4 p1, p2, p3, treeP;

        int c0 = seg * 8;
#pragma unroll 1
        for (int wi = 0; wi < 4; ++wi) {        // 4 words = 8 chunks
            unsigned word = s_bits[(c0 >> 1) + wi][bl];
#pragma unroll
            for (int hsel = 0; hsel < 2; ++hsel) {
                int lc = wi * 2 + hsel;
                unsigned half = hsel ? (word >> 16) : (word & 0xffffu);
                P4 s = chunk16(half, sW, (c0 + lc) * 16, qp, mx, mn);
                if (lc & 1) {
                    s = p4_add(p1, s);
                    if (lc & 2) {
                        s = p4_add(p2, s);
                        if (lc & 4) treeP = p4_add(p3, s);
                        else p3 = s;
                    } else p2 = s;
                } else p1 = s;
            }
        }
        if (seg == ES - 1) {
            // leftover chunk 48 (events 768..783): tree separate, snapshots
            // continue seg 5's local prefix.
            unsigned half = s_bits[24][bl] & 0xffffu;
            s_L[bl] = p4_unpack(chunk16(half, sW, 768, qp, mx, mn));
        }
        s_tree[seg][bl] = p4_unpack(treeP);
        s_px[seg][bl]   = mx;
        s_pn[seg][bl]   = mn;
        __syncthreads();

        if (seg == 0) {                         // 64 finalize threads, 1/batch
            const float4 m = *(const float4*)(h1_mem0 + n0);
            float4 o   = make_float4(0.f, 0.f, 0.f, 0.f);
            float4 gmx = make_float4(-CUDART_INF_F, -CUDART_INF_F, -CUDART_INF_F, -CUDART_INF_F);
            float4 gmn = make_float4( CUDART_INF_F,  CUDART_INF_F,  CUDART_INF_F,  CUDART_INF_F);
            float4 g0, g1, g2, prev;
#pragma unroll
            for (int i = 0; i < ES; ++i) {
                float4 tr = s_tree[i][bl];
                float4 px = s_px[i][bl];
                float4 pn = s_pn[i][bl];
                gmx.x = fmaxf(gmx.x, o.x + px.x); gmx.y = fmaxf(gmx.y, o.y + px.y);
                gmx.z = fmaxf(gmx.z, o.z + px.z); gmx.w = fmaxf(gmx.w, o.w + px.w);
                gmn.x = fminf(gmn.x, o.x + pn.x); gmn.y = fminf(gmn.y, o.y + pn.y);
                gmn.z = fminf(gmn.z, o.z + pn.z); gmn.w = fminf(gmn.w, o.w + pn.w);
                if ((i & 1) == 0) prev = tr;
                else {
                    float4 g = make_float4(prev.x + tr.x, prev.y + tr.y,
                                           prev.z + tr.z, prev.w + tr.w);
                    if (i == 1) g0 = g; else if (i == 3) g1 = g; else g2 = g;
                }
                o.x += tr.x; o.y += tr.y; o.z += tr.z; o.w += tr.w;
            }
            float4 L = s_L[bl];
            float4 f;
            f.x = m.x + (((g0.x + g1.x) + g2.x) + L.x);
            f.y = m.y + (((g0.y + g1.y) + g2.y) + L.y);
            f.z = m.z + (((g0.z + g1.z) + g2.z) + L.z);
            f.w = m.w + (((g0.w + g1.w) + g2.w) + L.w);

            float4 spk, hm;
            spk.x = f.x > THRESH ? 1.0f : 0.0f;  hm.x = f.x > THRESH ? 0.0f : f.x * DECAY;
            spk.y = f.y > THRESH ? 1.0f : 0.0f;  hm.y = f.y > THRESH ? 0.0f : f.y * DECAY;
            spk.z = f.z > THRESH ? 1.0f : 0.0f;  hm.z = f.z > THRESH ? 0.0f : f.z * DECAY;
            spk.w = f.w > THRESH ? 1.0f : 0.0f;  hm.w = f.w > THRESH ? 0.0f : f.w * DECAY;
            *(float4*)(g_spk + b * H + n0) = spk;
            *(float4*)(out_h1mem + b * H + n0) = hm;

            g_pmax[blockIdx.x * B + b] =
                fmaxf(fmaxf(m.x + gmx.x, m.y + gmx.y), fmaxf(m.z + gmx.z, m.w + gmx.w));
            g_pmin[blockIdx.x * B + b] =
                fminf(fminf(m.x + gmn.x, m.y + gmn.y), fminf(m.z + gmn.z, m.w + gmn.w));
        }
    }

    // -- Device-wide barrier (self-resetting via atomicInc wrap).
    __syncthreads();
    if (t == 0) {
        __threadfence();
        atomicInc(&g_bar, GRID_N - 1);   // 200th arrival wraps counter to 0
    }
    const int linear = blockIdx.y * NQ + blockIdx.x;
    if (linear >= B) return;             // non-spinner blocks done

    if (t == 0) {
        unsigned v;
        do {
            asm volatile("ld.acquire.gpu.u32 %0, [%1];" : "=r"(v) : "l"(&g_bar));
            if (v != 0) __nanosleep(64);
        } while (v != 0);
    }
    __syncthreads();

    // -- Phase 2: layer 2 + finalize for batch = linear.
    {
        const int b = linear;
        for (int i = t; i < H; i += NTHR) l2_spk[i] = g_spk[b * H + i];

        // layer-1 partial fold (max/min exactly associative)
        float fmx = -CUDART_INF_F, fmn = CUDART_INF_F;
        for (int k = t; k < NQ; k += NTHR) {
            fmx = fmaxf(fmx, g_pmax[k * B + b]);
            fmn = fminf(fmn, g_pmin[k * B + b]);
        }
#pragma unroll
        for (int off = 16; off > 0; off >>= 1) {
            fmx = fmaxf(fmx, __shfl_xor_sync(0xffffffffu, fmx, off));
            fmn = fminf(fmn, __shfl_xor_sync(0xffffffffu, fmn, off));
        }
        if (lane == 0) { l2_fmx[warp] = fmx; l2_fmn[warp] = fmn; }

        __syncthreads();   // l2_spk ready

        if (lane < OUT && warp < 4) {
            const float* w2 = W2 + lane * H;
            float q = 0.0f, px = -CUDART_INF_F, pn = CUDART_INF_F;
            float tr = 0.0f;
            if (warp < 3) {
                float pa, pb, pc;
#pragma unroll 1
                for (int lc = 0; lc < 8; ++lc) {
                    float s = chunk16_l2(l2_spk, w2, (warp * 8 + lc) * 16, q, px, pn);
                    if (lc & 1) { s = pa + s;
                        if (lc & 2) { s = pb + s;
                            if (lc & 4) { tr = pc + s; }
                            else pc = s;
                        } else pb = s;
                    } else pa = s;
                }
            } else {
                tr = chunk16_l2(l2_spk, w2, 384, q, px, pn);  // leftover chunk 24
            }
            l2_t[warp][lane]  = tr;
            l2_px[warp][lane] = px;
            l2_pn[warp][lane] = pn;
        }
        __syncthreads();

        if (t < OUT) {
            float t0 = l2_t[0][t], t1 = l2_t[1][t], t2 = l2_t[2][t], L = l2_t[3][t];
            float m0 = h2_mem0[t];
            float S = ((t0 + t1) + t2) + L;      // exact JAX tree for n=400
            float fin = m0 + S;
            float o1 = t0, o2 = t0 + t1, o3 = o2 + t2;
            float mxv = fmaxf(fmaxf(l2_px[0][t], o1 + l2_px[1][t]),
                              fmaxf(o2 + l2_px[2][t], o3 + l2_px[3][t]));
            float mnv = fminf(fminf(l2_pn[0][t], o1 + l2_pn[1][t]),
                              fminf(o2 + l2_pn[2][t], o3 + l2_pn[3][t]));
            l2_nmx[t] = m0 + mxv;
            l2_nmn[t] = m0 + mnv;
            bool sp = fin > THRESH;
            out_h2s[b * OUT + t]   = sp ? 1.0f : 0.0f;
            out_h2mem[b * OUT + t] = sp ? 0.0f : fin * DECAY;
        }
        __syncthreads();

        if (t == 0) {
            float mxv = l2_fmx[0], mnv = l2_fmn[0];
#pragma unroll
            for (int i = 1; i < NWARP; ++i) {
                mxv = fmaxf(mxv, l2_fmx[i]);
                mnv = fminf(mnv, l2_fmn[i]);
            }
#pragma unroll
            for (int i = 0; i < OUT; ++i) {
                mxv = fmaxf(mxv, l2_nmx[i]);
                mnv = fminf(mnv, l2_nmn[i]);
            }
            out_smax[b] = mxv;
            out_smin[b] = mnv;
        }
    }
}

// ---------------------------------------------------------------------------
// Launch. Output layout = flat concat of reference return tuple:
//   h2_spiked [B*OUT] | step_max [B] | step_min [B] | h1_mem [B*H] | h2_mem [B*OUT]
// ---------------------------------------------------------------------------
extern "C" void kernel_launch(void* const* d_in, const int* in_sizes, int n_in,
                              void* d_out, int out_size) {
    const float* input_vec = (const float*)d_in[0];
    const float* W1        = (const float*)d_in[1];
    const float* W2        = (const float*)d_in[2];
    const float* h1_mem0   = (const float*)d_in[3];
    const float* h2_mem0   = (const float*)d_in[4];

    k_fused<<<dim3(NQ, B / BG), NTHR>>>(input_vec, W1, W2, h1_mem0, h2_mem0,
                                        (float*)d_out);
}

// round 8
// speedup vs baseline: 1.3310x; 1.3310x over previous
#include <cuda_runtime.h>
#include <cuda_bf16.h>
#include <math_constants.h>

// Problem dims (fixed by reference setup_inputs)
#define B     128
#define H     400
#define IN    784
#define OUT   10
#define NQ    100              // H/4 neuron quads
#define BG    32               // batches per layer1 block
#define ES    12               // event segments (4 chunks = 64 events each)
#define NW    25               // ceil(784/32) bit words per batch
#define NTHR  (BG * ES)        // 384 threads

#define THRESH 0.5f
#define DECAY  0.2f

// Scratch (allocation-free rule: __device__ globals)
__device__ unsigned g_bits[NW * B];   // [word][batch] input spike bitmask
__device__ float    g_spk[B * H];     // h1 spikes as floats
__device__ float    g_pmax[NQ * B];   // per-(quad,batch) layer1 max partial
__device__ float    g_pmin[NQ * B];

// ---- packed f32x2 helpers (4 floats in 2x 64-bit regs) ----------------------
struct P4 { unsigned long long a, b; };

__device__ __forceinline__ P4 p4_zero() { P4 r; r.a = 0ull; r.b = 0ull; return r; }

__device__ __forceinline__ P4 p4_pack(float x, float y, float z, float w) {
    P4 r;
    asm("mov.b64 %0, {%2, %3};\n\tmov.b64 %1, {%4, %5};"
        : "=l"(r.a), "=l"(r.b) : "f"(x), "f"(y), "f"(z), "f"(w));
    return r;
}
__device__ __forceinline__ float4 p4_unpack(P4 p) {
    float4 v;
    asm("mov.b64 {%0, %1}, %4;\n\tmov.b64 {%2, %3}, %5;"
        : "=f"(v.x), "=f"(v.y), "=f"(v.z), "=f"(v.w) : "l"(p.a), "l"(p.b));
    return v;
}
__device__ __forceinline__ P4 p4_add(P4 u, P4 v) {
    P4 r;
    asm("add.rn.f32x2 %0, %2, %3;\n\tadd.rn.f32x2 %1, %4, %5;"
        : "=l"(r.a), "=l"(r.b) : "l"(u.a), "l"(v.a), "l"(u.b), "l"(v.b));
    return r;
}

// ---------------------------------------------------------------------------
// Kernel 0: pack input_vec (B x IN, {0,1} floats) into bit words, transposed
// layout g_bits[w*B + b]. One warp per word: single load + ballot.
// ---------------------------------------------------------------------------
__global__ __launch_bounds__(800) void k_pack(const float* __restrict__ input_vec) {
    int b = blockIdx.x;
    int t = threadIdx.x;
    int w = t >> 5;
    int lane = t & 31;
    float v = (t < IN) ? input_vec[b * IN + t] : 0.0f;
    unsigned m = __ballot_sync(0xffffffffu, v != 0.0f);
    if (lane == 0) g_bits[w * B + b] = m;
}

// ---------------------------------------------------------------------------
// chunk16: 16 consecutive events, 4 neurons. Sign-mask gating (bitwise exact:
// gated-off leaf contributes +0.0f). Running packed prefix qp feeds per-leaf
// scalar max/min snapshots (unpack = register aliasing). Returns the
// balanced-16 pairwise tree sum of the gated weights via a leaf-level binary
// counter (identical association to the R5-passing kernel).
// ---------------------------------------------------------------------------
__device__ __forceinline__ P4 chunk16(
    unsigned half, const float4* __restrict__ sW, int ebase,
    P4& qp, float4& mx, float4& mn)
{
    P4 k1, k2, k4, k8, out;
#pragma unroll
    for (int j = 0; j < 16; ++j) {
        int msk = ((int)(half << (31 - j))) >> 31;   // all-ones if bit j set
        float4 w = sW[ebase + j];
        float tx = __int_as_float(msk & __float_as_int(w.x));
        float ty = __int_as_float(msk & __float_as_int(w.y));
        float tz = __int_as_float(msk & __float_as_int(w.z));
        float tw = __int_as_float(msk & __float_as_int(w.w));
        P4 tp = p4_pack(tx, ty, tz, tw);
        qp = p4_add(qp, tp);                         // exact when gated off
        float4 q = p4_unpack(qp);
        mx.x = fmaxf(mx.x, q.x); mx.y = fmaxf(mx.y, q.y);
        mx.z = fmaxf(mx.z, q.z); mx.w = fmaxf(mx.w, q.w);
        mn.x = fminf(mn.x, q.x); mn.y = fminf(mn.y, q.y);
        mn.z = fminf(mn.z, q.z); mn.w = fminf(mn.w, q.w);
        if ((j & 1) == 0) {
            k1 = tp;
        } else {
            P4 s = p4_add(k1, tp);
            if ((j & 2) == 0) k2 = s;
            else {
                s = p4_add(k2, s);
                if ((j & 4) == 0) k4 = s;
                else {
                    s = p4_add(k4, s);
                    if (j == 7) k8 = s;
                    else out = p4_add(k8, s);        // j == 15
                }
            }
        }
    }
    return out;
}

// ---------------------------------------------------------------------------
// Kernel 1: layer 1. Block = 4 neurons x 32 batches x 12 event segments
// (384 threads, warp = one segment for 32 batches). Segment s handles chunks
// [4s, 4s+4) (64 events) -> bal64 via a 2-level counter; seg 11 additionally
// does leftover chunk 48 (events 768..783) with its tree kept separate but
// snapshots continuing seg 11's local prefix.
// Recombination reproduces the R2-verified JAX tree bitwise:
//   t_i = u_{2i} + u_{2i+1}   (bal128 = bal64_lo + bal64_hi)
//   S   = (((t0+t1) + (t2+t3)) + (t4+t5)) + L
// Snapshot max/min recombined with running segment-total offsets (approx,
// tol 1e-3; passes at 1.5e-7).
// ---------------------------------------------------------------------------
__global__ __launch_bounds__(NTHR, 2) void k_layer1(
    const float* __restrict__ W1,       // [H][IN]
    const float* __restrict__ h1_mem0,  // [H]
    float* __restrict__ out_h1mem)      // [B][H] (slice of d_out)
{
    __shared__ float4 sW[IN];                 // sW[e] = (w_n0..w_n3)[e]
    __shared__ float4 s_tree[ES][BG];
    __shared__ float4 s_px[ES][BG];
    __shared__ float4 s_pn[ES][BG];
    __shared__ float4 s_L[BG];

    const int t   = threadIdx.x;
    const int seg = t >> 5;                   // 0..11 (one warp per segment)
    const int bl  = t & 31;                   // local batch
    const int b   = blockIdx.y * BG + bl;     // global batch
    const int n0  = blockIdx.x * 4;           // neuron quad base

    // Stage weights: smem[e] = (W1[n0][e], .., W1[n0+3][e])
    for (int i = t; i < 4 * IN; i += NTHR) {
        int c = i / IN;
        int e = i - c * IN;
        ((float*)sW)[e * 4 + c] = W1[(n0 + c) * IN + e];
    }
    __syncthreads();

    P4 qp = p4_zero();                        // local weight prefix (from 0)
    float4 mx = make_float4(-CUDART_INF_F, -CUDART_INF_F, -CUDART_INF_F, -CUDART_INF_F);
    float4 mn = make_float4( CUDART_INF_F,  CUDART_INF_F,  CUDART_INF_F,  CUDART_INF_F);
    P4 p1, p2, treeP;

    const int c0 = seg * 4;                   // first chunk of this segment
#pragma unroll
    for (int wi = 0; wi < 2; ++wi) {          // 2 words = 4 chunks
        unsigned word = g_bits[((c0 >> 1) + wi) * B + b];
#pragma unroll
        for (int hsel = 0; hsel < 2; ++hsel) {
            int lc = wi * 2 + hsel;
            unsigned half = hsel ? (word >> 16) : (word & 0xffffu);
            P4 s = chunk16(half, sW, (c0 + lc) * 16, qp, mx, mn);
            if (lc & 1) {
                s = p4_add(p1, s);
                if (lc & 2) treeP = p4_add(p2, s);   // lc == 3
                else p2 = s;                          // lc == 1
            } else p1 = s;
        }
    }
    if (seg == ES - 1) {
        // leftover chunk 48 (events 768..783): tree separate, snapshots
        // continue seg 11's local prefix.
        unsigned half = g_bits[24 * B + b] & 0xffffu;
        s_L[bl] = p4_unpack(chunk16(half, sW, 768, qp, mx, mn));
    }
    s_tree[seg][bl] = p4_unpack(treeP);
    s_px[seg][bl]   = mx;
    s_pn[seg][bl]   = mn;
    __syncthreads();

    if (seg == 0) {                           // 32 finalize threads, 1/batch
        const float4 m = *(const float4*)(h1_mem0 + n0);

        // Pass 1: snapshot recombination with running offsets
        float4 o   = make_float4(0.f, 0.f, 0.f, 0.f);
        float4 gmx = make_float4(-CUDART_INF_F, -CUDART_INF_F, -CUDART_INF_F, -CUDART_INF_F);
        float4 gmn = make_float4( CUDART_INF_F,  CUDART_INF_F,  CUDART_INF_F,  CUDART_INF_F);
#pragma unroll
        for (int i = 0; i < ES; ++i) {
            float4 tr = s_tree[i][bl];
            float4 px = s_px[i][bl];
            float4 pn = s_pn[i][bl];
            gmx.x = fmaxf(gmx.x, o.x + px.x); gmx.y = fmaxf(gmx.y, o.y + px.y);
            gmx.z = fmaxf(gmx.z, o.z + px.z); gmx.w = fmaxf(gmx.w, o.w + px.w);
            gmn.x = fminf(gmn.x, o.x + pn.x); gmn.y = fminf(gmn.y, o.y + pn.y);
            gmn.z = fminf(gmn.z, o.z + pn.z); gmn.w = fminf(gmn.w, o.w + pn.w);
            o.x += tr.x; o.y += tr.y; o.z += tr.z; o.w += tr.w;
        }

        // Pass 2: exact tree recombination t_i = u_{2i}+u_{2i+1};
        // S = (((t0+t1)+(t2+t3))+(t4+t5)) + L
        float4 tt[6];
#pragma unroll
        for (int i = 0; i < 6; ++i) {
            float4 ua = s_tree[2 * i][bl];
            float4 ub = s_tree[2 * i + 1][bl];
            tt[i] = make_float4(ua.x + ub.x, ua.y + ub.y, ua.z + ub.z, ua.w + ub.w);
        }
        float4 L = s_L[bl];
        float4 f;
        f.x = m.x + ((((tt[0].x + tt[1].x) + (tt[2].x + tt[3].x)) + (tt[4].x + tt[5].x)) + L.x);
        f.y = m.y + ((((tt[0].y + tt[1].y) + (tt[2].y + tt[3].y)) + (tt[4].y + tt[5].y)) + L.y);
        f.z = m.z + ((((tt[0].z + tt[1].z) + (tt[2].z + tt[3].z)) + (tt[4].z + tt[5].z)) + L.z);
        f.w = m.w + ((((tt[0].w + tt[1].w) + (tt[2].w + tt[3].w)) + (tt[4].w + tt[5].w)) + L.w);

        float4 spk, hm;
        spk.x = f.x > THRESH ? 1.0f : 0.0f;  hm.x = f.x > THRESH ? 0.0f : f.x * DECAY;
        spk.y = f.y > THRESH ? 1.0f : 0.0f;  hm.y = f.y > THRESH ? 0.0f : f.y * DECAY;
        spk.z = f.z > THRESH ? 1.0f : 0.0f;  hm.z = f.z > THRESH ? 0.0f : f.z * DECAY;
        spk.w = f.w > THRESH ? 1.0f : 0.0f;  hm.w = f.w > THRESH ? 0.0f : f.w * DECAY;
        *(float4*)(g_spk + b * H + n0) = spk;
        *(float4*)(out_h1mem + b * H + n0) = hm;

        g_pmax[blockIdx.x * B + b] =
            fmaxf(fmaxf(m.x + gmx.x, m.y + gmx.y), fmaxf(m.z + gmx.z, m.w + gmx.w));
        g_pmin[blockIdx.x * B + b] =
            fminf(fminf(m.x + gmn.x, m.y + gmn.y), fminf(m.z + gmn.z, m.w + gmn.w));
    }
}

// ---------------------------------------------------------------------------
// chunk16 for layer 2 (1 neuron): gate = spike float (exactly 0.0/1.0).
// ---------------------------------------------------------------------------
__device__ __forceinline__ float chunk16_l2(
    const float* __restrict__ spk, const float* __restrict__ w2, int ebase,
    float& q, float& mx, float& mn)
{
    float s[16];
#pragma unroll
    for (int j = 0; j < 16; ++j) {
        float t = spk[ebase + j] * w2[ebase + j];   // exact: 0 or w
        q += t;
        mx = fmaxf(mx, q);
        mn = fminf(mn, q);
        s[j] = t;
    }
#pragma unroll
    for (int st = 1; st < 16; st <<= 1)
#pragma unroll
        for (int j = 0; j < 16; j += 2 * st) s[j] += s[j + st];
    return s[0];
}

// ---------------------------------------------------------------------------
// Kernel 2: layer 2 + finalize. Block = one batch, 128 threads (4 warps).
// Warps 0..2: one bal128 group each (8 chunks, lanes 0..9 = neurons);
// warp 3: leftover chunk 24 (events 384..399). All 128 threads fold the
// layer-1 partials. Recombination: S = ((t0 + t1) + t2) + L.
// ---------------------------------------------------------------------------
__global__ __launch_bounds__(128) void k_layer2(
    const float* __restrict__ W2,       // [OUT][H]
    const float* __restrict__ h2_mem0,  // [OUT]
    float* __restrict__ out_h2s,        // [B][OUT]
    float* __restrict__ out_smax,       // [B]
    float* __restrict__ out_smin,       // [B]
    float* __restrict__ out_h2mem)      // [B][OUT]
{
    __shared__ float spk[H];
    __shared__ float s_t[4][OUT], s_px[4][OUT], s_pn[4][OUT];
    __shared__ float s_fmx[4], s_fmn[4];
    __shared__ float s_nmx[OUT], s_nmn[OUT];

    int b = blockIdx.x;
    int t = threadIdx.x;
    int w = t >> 5;
    int lane = t & 31;

    for (int i = t; i < H; i += 128) spk[i] = g_spk[b * H + i];

    // layer-1 partial fold (max/min exactly associative)
    float fmx = -CUDART_INF_F, fmn = CUDART_INF_F;
    for (int k = t; k < NQ; k += 128) {
        fmx = fmaxf(fmx, g_pmax[k * B + b]);
        fmn = fminf(fmn, g_pmin[k * B + b]);
    }
#pragma unroll
    for (int off = 16; off > 0; off >>= 1) {
        fmx = fmaxf(fmx, __shfl_xor_sync(0xffffffffu, fmx, off));
        fmn = fminf(fmn, __shfl_xor_sync(0xffffffffu, fmn, off));
    }
    if (lane == 0) { s_fmx[w] = fmx; s_fmn[w] = fmn; }

    __syncthreads();   // spk ready

    if (lane < OUT) {
        const float* w2 = W2 + lane * H;
        float q = 0.0f, px = -CUDART_INF_F, pn = CUDART_INF_F;
        float tr = 0.0f;
        if (w < 3) {
            float pa, pb, pc;
#pragma unroll 1
            for (int lc = 0; lc < 8; ++lc) {
                float s = chunk16_l2(spk, w2, (w * 8 + lc) * 16, q, px, pn);
                if (lc & 1) { s = pa + s;
                    if (lc & 2) { s = pb + s;
                        if (lc & 4) { tr = pc + s; }
                        else pc = s;
                    } else pb = s;
                } else pa = s;
            }
        } else {
            tr = chunk16_l2(spk, w2, 384, q, px, pn);  // leftover chunk 24
        }
        s_t[w][lane]  = tr;
        s_px[w][lane] = px;
        s_pn[w][lane] = pn;
    }
    __syncthreads();

    if (t < OUT) {
        float t0 = s_t[0][t], t1 = s_t[1][t], t2 = s_t[2][t], L = s_t[3][t];
        float m0 = h2_mem0[t];
        float S = ((t0 + t1) + t2) + L;
        float fin = m0 + S;
        float o1 = t0, o2 = t0 + t1, o3 = o2 + t2;
        float mx = fmaxf(fmaxf(s_px[0][t], o1 + s_px[1][t]),
                         fmaxf(o2 + s_px[2][t], o3 + s_px[3][t]));
        float mn = fminf(fminf(s_pn[0][t], o1 + s_pn[1][t]),
                         fminf(o2 + s_pn[2][t], o3 + s_pn[3][t]));
        s_nmx[t] = m0 + mx;
        s_nmn[t] = m0 + mn;
        bool sp = fin > THRESH;
        out_h2s[b * OUT + t]   = sp ? 1.0f : 0.0f;
        out_h2mem[b * OUT + t] = sp ? 0.0f : fin * DECAY;
    }
    __syncthreads();

    if (t == 0) {
        float mx = fmaxf(fmaxf(s_fmx[0], s_fmx[1]), fmaxf(s_fmx[2], s_fmx[3]));
        float mn = fminf(fminf(s_fmn[0], s_fmn[1]), fminf(s_fmn[2], s_fmn[3]));
#pragma unroll
        for (int i = 0; i < OUT; ++i) {
            mx = fmaxf(mx, s_nmx[i]);
            mn = fminf(mn, s_nmn[i]);
        }
        out_smax[b] = mx;
        out_smin[b] = mn;
    }
}

// ---------------------------------------------------------------------------
// Launch. Output layout = flat concat of reference return tuple:
//   h2_spiked [B*OUT] | step_max [B] | step_min [B] | h1_mem [B*H] | h2_mem [B*OUT]
// ---------------------------------------------------------------------------
extern "C" void kernel_launch(void* const* d_in, const int* in_sizes, int n_in,
                              void* d_out, int out_size) {
    const float* input_vec = (const float*)d_in[0];
    const float* W1        = (const float*)d_in[1];
    const float* W2        = (const float*)d_in[2];
    const float* h1_mem0   = (const float*)d_in[3];
    const float* h2_mem0   = (const float*)d_in[4];

    float* out = (float*)d_out;
    float* out_h2s   = out;                            // B*OUT
    float* out_smax  = out + B * OUT;                  // B
    float* out_smin  = out + B * OUT + B;              // B
    float* out_h1mem = out + B * OUT + 2 * B;          // B*H
    float* out_h2mem = out + B * OUT + 2 * B + B * H;  // B*OUT

    k_pack<<<B, 800>>>(input_vec);
    k_layer1<<<dim3(NQ, B / BG), NTHR>>>(W1, h1_mem0, out_h1mem);
    k_layer2<<<B, 128>>>(W2, h2_mem0, out_h2s, out_smax, out_smin, out_h2mem);
}